// round 1
// baseline (speedup 1.0000x reference)
#include <cuda_runtime.h>

// Problem constants (fixed by the dataset)
#define D_H   2048          // hidden size
#define T_LEN 4096          // sequence length
#define B_SZ  2             // batch
#define NROWS (B_SZ * T_LEN) // 8192 total rows
#define G_DIM 2048          // generator hidden
#define KW    4             // conv kernel width
#define FLATC (D_H * KW)    // 8192 flat columns

// GEMM tiling
#define BM 128
#define BN 128
#define BK 16
#define TM 8
#define TN 8
// threads = (BM/TM)*(BN/TN) = 16*16 = 256

// 64 MB scratch for H = silu(X @ W1^T)  (device global: allocation-free)
__device__ float g_H[(size_t)NROWS * G_DIM];

__device__ __forceinline__ float silu_f(float v) {
    return v / (1.0f + __expf(-v));
}

// ---------------------------------------------------------------------------
// GEMM1: g_H[n,g] = silu( sum_d X[n,d] * W1[g,d] )
// X: [NROWS, D_H] row-major, W1: [G_DIM, D_H] row-major (NT gemm)
// ---------------------------------------------------------------------------
__global__ __launch_bounds__(256)
void gemm1_silu(const float* __restrict__ X, const float* __restrict__ W1) {
    __shared__ float As[BK][BM];
    __shared__ float Bs[BK][BN];

    const int tid = threadIdx.x;
    const int tx = tid & 15;   // 0..15 -> output col group
    const int ty = tid >> 4;   // 0..15 -> output row group
    const int row0 = blockIdx.y * BM;
    const int col0 = blockIdx.x * BN;

    float acc[TM][TN];
#pragma unroll
    for (int i = 0; i < TM; i++)
#pragma unroll
        for (int j = 0; j < TN; j++) acc[i][j] = 0.0f;

    for (int k0 = 0; k0 < D_H; k0 += BK) {
        // Load 128x16 A tile and 128x16 B tile, transposed into smem.
        // 512 float4 per tile, 2 per thread.
#pragma unroll
        for (int jj = 0; jj < 2; jj++) {
            int idx = tid * 2 + jj;          // 0..511
            int r  = idx >> 2;               // row within tile 0..127
            int c4 = idx & 3;                // float4 within row 0..3
            float4 va = *(const float4*)(X  + (size_t)(row0 + r) * D_H + k0 + c4 * 4);
            As[c4 * 4 + 0][r] = va.x;
            As[c4 * 4 + 1][r] = va.y;
            As[c4 * 4 + 2][r] = va.z;
            As[c4 * 4 + 3][r] = va.w;
            float4 vb = *(const float4*)(W1 + (size_t)(col0 + r) * D_H + k0 + c4 * 4);
            Bs[c4 * 4 + 0][r] = vb.x;
            Bs[c4 * 4 + 1][r] = vb.y;
            Bs[c4 * 4 + 2][r] = vb.z;
            Bs[c4 * 4 + 3][r] = vb.w;
        }
        __syncthreads();

#pragma unroll
        for (int k = 0; k < BK; k++) {
            float a[TM], b[TN];
#pragma unroll
            for (int i = 0; i < TM; i++) a[i] = As[k][ty * TM + i];
#pragma unroll
            for (int j = 0; j < TN; j++) b[j] = Bs[k][tx * TN + j];
#pragma unroll
            for (int i = 0; i < TM; i++)
#pragma unroll
                for (int j = 0; j < TN; j++) acc[i][j] = fmaf(a[i], b[j], acc[i][j]);
        }
        __syncthreads();
    }

    // Epilogue: silu + store to g_H
#pragma unroll
    for (int i = 0; i < TM; i++) {
        int n = row0 + ty * TM + i;
#pragma unroll
        for (int j = 0; j < TN; j += 4) {
            int g = col0 + tx * TN + j;
            float4 o;
            o.x = silu_f(acc[i][j + 0]);
            o.y = silu_f(acc[i][j + 1]);
            o.z = silu_f(acc[i][j + 2]);
            o.w = silu_f(acc[i][j + 3]);
            *(float4*)(g_H + (size_t)n * G_DIM + g) = o;
        }
    }
}

// ---------------------------------------------------------------------------
// GEMM2 + fused conv:
//   flat[n,c] = sum_g H[n,g] * W2[c,g] + b2[c]   (c = 4*d + w)
//   y[n,d]    = silu( sum_w xpad[t-3+w, d] * flat[n, 4d+w] )
// Tile layout: BN=128 flat columns = 32 d's; each thread's 8 columns are
// exactly 2 consecutive d's x 4 taps -> conv done fully in registers.
// ---------------------------------------------------------------------------
__global__ __launch_bounds__(256)
void gemm2_conv_silu(const float* __restrict__ X,
                     const float* __restrict__ W2,
                     const float* __restrict__ b2,
                     float* __restrict__ out) {
    __shared__ float As[BK][BM];
    __shared__ float Bs[BK][BN];

    const int tid = threadIdx.x;
    const int tx = tid & 15;
    const int ty = tid >> 4;
    const int row0 = blockIdx.y * BM;  // n
    const int col0 = blockIdx.x * BN;  // flat column

    float acc[TM][TN];
#pragma unroll
    for (int i = 0; i < TM; i++)
#pragma unroll
        for (int j = 0; j < TN; j++) acc[i][j] = 0.0f;

    for (int k0 = 0; k0 < G_DIM; k0 += BK) {
#pragma unroll
        for (int jj = 0; jj < 2; jj++) {
            int idx = tid * 2 + jj;
            int r  = idx >> 2;
            int c4 = idx & 3;
            float4 va = *(const float4*)(g_H + (size_t)(row0 + r) * G_DIM + k0 + c4 * 4);
            As[c4 * 4 + 0][r] = va.x;
            As[c4 * 4 + 1][r] = va.y;
            As[c4 * 4 + 2][r] = va.z;
            As[c4 * 4 + 3][r] = va.w;
            float4 vb = *(const float4*)(W2 + (size_t)(col0 + r) * G_DIM + k0 + c4 * 4);
            Bs[c4 * 4 + 0][r] = vb.x;
            Bs[c4 * 4 + 1][r] = vb.y;
            Bs[c4 * 4 + 2][r] = vb.z;
            Bs[c4 * 4 + 3][r] = vb.w;
        }
        __syncthreads();

#pragma unroll
        for (int k = 0; k < BK; k++) {
            float a[TM], b[TN];
#pragma unroll
            for (int i = 0; i < TM; i++) a[i] = As[k][ty * TM + i];
#pragma unroll
            for (int j = 0; j < TN; j++) b[j] = Bs[k][tx * TN + j];
#pragma unroll
            for (int i = 0; i < TM; i++)
#pragma unroll
                for (int j = 0; j < TN; j++) acc[i][j] = fmaf(a[i], b[j], acc[i][j]);
        }
        __syncthreads();
    }

    // Epilogue: bias + causal depthwise conv + silu
    const int cbase = col0 + tx * TN;          // multiple of 8
    float bias[TN];
#pragma unroll
    for (int j = 0; j < TN; j++) bias[j] = b2[cbase + j];

#pragma unroll
    for (int i = 0; i < TM; i++) {
        int n = row0 + ty * TM + i;
        int bb = n / T_LEN;
        int t  = n - bb * T_LEN;
#pragma unroll
        for (int dd = 0; dd < 2; dd++) {
            int c = cbase + dd * KW;
            int d = c >> 2;                    // feature index
            float y = 0.0f;
#pragma unroll
            for (int w = 0; w < KW; w++) {
                int tt = t - (KW - 1) + w;
                float kv = acc[i][dd * KW + w] + bias[dd * KW + w];
                if (tt >= 0) {
                    y = fmaf(X[((size_t)bb * T_LEN + tt) * D_H + d], kv, y);
                }
            }
            out[(size_t)n * D_H + d] = silu_f(y);
        }
    }
}

// ---------------------------------------------------------------------------
extern "C" void kernel_launch(void* const* d_in, const int* in_sizes, int n_in,
                              void* d_out, int out_size) {
    const float* x  = (const float*)d_in[0];  // [2,4096,2048]
    const float* w1 = (const float*)d_in[1];  // [2048,2048]
    const float* w2 = (const float*)d_in[2];  // [8192,2048]
    const float* b2 = (const float*)d_in[3];  // [8192]
    float* out = (float*)d_out;               // [2,4096,2048]

    dim3 block(256);
    dim3 grid1(G_DIM / BN, NROWS / BM);    // (16, 64)
    gemm1_silu<<<grid1, block>>>(x, w1);

    dim3 grid2(FLATC / BN, NROWS / BM);    // (64, 64)
    gemm2_conv_silu<<<grid2, block>>>(x, w2, b2, out);
}

// round 3
// speedup vs baseline: 2.6696x; 2.6696x over previous
#include <cuda_runtime.h>
#include <cstdint>

// Problem constants
#define D_H   2048
#define T_LEN 4096
#define B_SZ  2
#define NROWS (B_SZ * T_LEN)   // 8192
#define G_DIM 2048
#define KW    4
#define FLATC (D_H * KW)       // 8192

// Tiling
#define BM 128
#define BN 128
#define BK 16
#define PAD 20                 // smem row stride in 32-bit words (conflict-free)
#define NKT 2                  // k-steps of 8 per BK tile

// 64 MB scratch for H = silu(X @ W1^T)
__device__ float g_H[(size_t)NROWS * G_DIM];

__device__ __forceinline__ float silu_f(float v) {
    return v / (1.0f + __expf(-v));
}

__device__ __forceinline__ uint32_t f2tf32(float x) {
    uint32_t r;
    asm("cvt.rna.tf32.f32 %0, %1;" : "=r"(r) : "f"(x));
    return r;
}

__device__ __forceinline__ void mma_tf32(float c[4], const uint32_t a[4], const uint32_t b[2]) {
    asm volatile(
        "mma.sync.aligned.m16n8k8.row.col.f32.tf32.tf32.f32 "
        "{%0,%1,%2,%3}, {%4,%5,%6,%7}, {%8,%9}, {%0,%1,%2,%3};"
        : "+f"(c[0]), "+f"(c[1]), "+f"(c[2]), "+f"(c[3])
        : "r"(a[0]), "r"(a[1]), "r"(a[2]), "r"(a[3]), "r"(b[0]), "r"(b[1]));
}

// ---------------------------------------------------------------------------
// Shared tf32 GEMM mainloop: C[128x128] += A[128xK] * B[128xK]^T (NT)
// EPI=0: silu -> g_H      EPI=1: A := g_H (device symbol); bias+conv+silu -> out
// ---------------------------------------------------------------------------
template <int EPI>
__global__ __launch_bounds__(256, 2)
void gemm_tf32_fused(const float* __restrict__ A_in,
                     const float* __restrict__ B,
                     int K,
                     const float* __restrict__ X,    // EPI=1 only
                     const float* __restrict__ b2,   // EPI=1 only
                     float* __restrict__ out) {      // EPI=1 only
    // CRITICAL: __device__ globals must be referenced from device code.
    const float* A = (EPI == 1) ? (const float*)g_H : A_in;

    __shared__ uint32_t As[2][BM * PAD];
    __shared__ uint32_t Bs[2][BM * PAD];

    const int tid  = threadIdx.x;
    const int lane = tid & 31;
    const int warp = tid >> 5;
    const int wm = warp & 3;            // 0..3  (M)
    const int wn = warp >> 2;           // 0..1  (N)
    const int row0 = blockIdx.y * BM;
    const int col0 = blockIdx.x * BN;

    // global load mapping: 512 float4 per tile, 2 per thread
    const int ldr  = tid >> 2;          // 0..63 base row, +64 for i=1
    const int ldc4 = tid & 3;           // float4 index within 16-wide row

    float acc[2][8][4];
#pragma unroll
    for (int i = 0; i < 2; i++)
#pragma unroll
        for (int j = 0; j < 8; j++)
#pragma unroll
            for (int k = 0; k < 4; k++) acc[i][j][k] = 0.0f;

    // ---- initial tile load (kt = 0) ----
    {
#pragma unroll
        for (int i = 0; i < 2; i++) {
            int r = ldr + i * 64;
            float4 va = *(const float4*)(A + (size_t)(row0 + r) * K + ldc4 * 4);
            float4 vb = *(const float4*)(B + (size_t)(col0 + r) * K + ldc4 * 4);
            uint32_t* pa = &As[0][r * PAD + ldc4 * 4];
            uint32_t* pb = &Bs[0][r * PAD + ldc4 * 4];
            pa[0] = f2tf32(va.x); pa[1] = f2tf32(va.y); pa[2] = f2tf32(va.z); pa[3] = f2tf32(va.w);
            pb[0] = f2tf32(vb.x); pb[1] = f2tf32(vb.y); pb[2] = f2tf32(vb.z); pb[3] = f2tf32(vb.w);
        }
    }
    __syncthreads();

    const int nkt = K / BK;             // 128
    const int arow = wm * 32 + (lane >> 2);
    const int brow = wn * 64 + (lane >> 2);
    const int kq = lane & 3;

    for (int kt = 0; kt < nkt; kt++) {
        const int cur = kt & 1;

        // prefetch next tile into registers (overlaps with compute)
        float4 ra[2], rb[2];
        if (kt + 1 < nkt) {
            int k0 = (kt + 1) * BK;
#pragma unroll
            for (int i = 0; i < 2; i++) {
                int r = ldr + i * 64;
                ra[i] = *(const float4*)(A + (size_t)(row0 + r) * K + k0 + ldc4 * 4);
                rb[i] = *(const float4*)(B + (size_t)(col0 + r) * K + k0 + ldc4 * 4);
            }
        }

        // compute: 2 k-steps of 8
        const uint32_t* Ab = As[cur];
        const uint32_t* Bb = Bs[cur];
#pragma unroll
        for (int ks = 0; ks < NKT; ks++) {
            const int kf = ks * 8 + kq;
            uint32_t afr[2][4];
#pragma unroll
            for (int mt = 0; mt < 2; mt++) {
                int rr = (arow + mt * 16) * PAD;
                afr[mt][0] = Ab[rr + kf];
                afr[mt][1] = Ab[rr + 8 * PAD + kf];
                afr[mt][2] = Ab[rr + kf + 4];
                afr[mt][3] = Ab[rr + 8 * PAD + kf + 4];
            }
            uint32_t bfr[8][2];
#pragma unroll
            for (int nt = 0; nt < 8; nt++) {
                int rr = (brow + nt * 8) * PAD;
                bfr[nt][0] = Bb[rr + kf];
                bfr[nt][1] = Bb[rr + kf + 4];
            }
#pragma unroll
            for (int mt = 0; mt < 2; mt++)
#pragma unroll
                for (int nt = 0; nt < 8; nt++)
                    mma_tf32(acc[mt][nt], afr[mt], bfr[nt]);
        }

        // store prefetched tile into the other buffer
        if (kt + 1 < nkt) {
            int nxt = 1 - cur;
#pragma unroll
            for (int i = 0; i < 2; i++) {
                int r = ldr + i * 64;
                uint32_t* pa = &As[nxt][r * PAD + ldc4 * 4];
                uint32_t* pb = &Bs[nxt][r * PAD + ldc4 * 4];
                pa[0] = f2tf32(ra[i].x); pa[1] = f2tf32(ra[i].y);
                pa[2] = f2tf32(ra[i].z); pa[3] = f2tf32(ra[i].w);
                pb[0] = f2tf32(rb[i].x); pb[1] = f2tf32(rb[i].y);
                pb[2] = f2tf32(rb[i].z); pb[3] = f2tf32(rb[i].w);
            }
        }
        __syncthreads();
    }

    // ---- epilogue ----
    const int q = lane & 3;

    if (EPI == 0) {
        // silu -> g_H
#pragma unroll
        for (int mt = 0; mt < 2; mt++) {
            int n = row0 + wm * 32 + mt * 16 + (lane >> 2);
#pragma unroll
            for (int nt = 0; nt < 8; nt++) {
                int g = col0 + wn * 64 + nt * 8 + 2 * q;
                float2 v0 = make_float2(silu_f(acc[mt][nt][0]), silu_f(acc[mt][nt][1]));
                float2 v1 = make_float2(silu_f(acc[mt][nt][2]), silu_f(acc[mt][nt][3]));
                *(float2*)(g_H + (size_t)n * G_DIM + g) = v0;
                *(float2*)(g_H + (size_t)(n + 8) * G_DIM + g) = v1;
            }
        }
    } else {
        // bias + causal depthwise conv + silu -> out
        // thread's two flat columns: c = cb + 2q, cb+2q+1
        // d = cb/4 + (q>>1); taps wa = 2*(q&1), wa+1. shfl_xor(1) pairs tap halves.
        const int halfd = q >> 1;
        const int wa = (q & 1) * 2;
#pragma unroll
        for (int nt = 0; nt < 8; nt++) {
            const int cb = col0 + wn * 64 + nt * 8;
            const int d  = (cb >> 2) + halfd;
            const float bias0 = b2[cb + 2 * q];
            const float bias1 = b2[cb + 2 * q + 1];
#pragma unroll
            for (int mt = 0; mt < 2; mt++) {
#pragma unroll
                for (int h = 0; h < 2; h++) {
                    const int n = row0 + wm * 32 + mt * 16 + (lane >> 2) + h * 8;
                    const int bb = n >> 12;             // /T_LEN
                    const int t  = n & (T_LEN - 1);
                    const float k0 = acc[mt][nt][2 * h + 0] + bias0;
                    const float k1 = acc[mt][nt][2 * h + 1] + bias1;
                    const float* xb = X + (size_t)bb * T_LEN * D_H + d;
                    float partial = 0.0f;
                    const int tt0 = t - (KW - 1) + wa;
                    if (tt0 >= 0)     partial = fmaf(xb[(size_t)tt0 * D_H], k0, partial);
                    if (tt0 + 1 >= 0) partial = fmaf(xb[(size_t)(tt0 + 1) * D_H], k1, partial);
                    const float tot = partial + __shfl_xor_sync(0xffffffffu, partial, 1);
                    if ((q & 1) == 0)
                        out[(size_t)n * D_H + d] = silu_f(tot);
                }
            }
        }
    }
}

// ---------------------------------------------------------------------------
extern "C" void kernel_launch(void* const* d_in, const int* in_sizes, int n_in,
                              void* d_out, int out_size) {
    const float* x  = (const float*)d_in[0];  // [2,4096,2048]
    const float* w1 = (const float*)d_in[1];  // [2048,2048]
    const float* w2 = (const float*)d_in[2];  // [8192,2048]
    const float* b2 = (const float*)d_in[3];  // [8192]
    float* out = (float*)d_out;               // [2,4096,2048]

    dim3 block(256);

    // GEMM1: g_H = silu(X @ W1^T)   [8192 x 2048]
    dim3 grid1(G_DIM / BN, NROWS / BM);       // (16, 64)
    gemm_tf32_fused<0><<<grid1, block>>>(x, w1, D_H, nullptr, nullptr, nullptr);

    // GEMM2 + conv (A bound to g_H inside the kernel — device-side symbol ref)
    dim3 grid2(FLATC / BN, NROWS / BM);       // (64, 64)
    gemm_tf32_fused<1><<<grid2, block>>>(nullptr, w2, G_DIM, x, b2, out);
}

// round 5
// speedup vs baseline: 3.7975x; 1.4225x over previous
#include <cuda_runtime.h>
#include <cstdint>

// ---------------- problem constants ----------------
#define D_H   2048
#define T_LEN 4096
#define NROWS 8192
#define G_DIM 2048
#define KW    4
#define FLATC 8192
#define KDIM  2048

// ---------------- tiling ----------------
#define BM 128
#define BN 128
#define BK 32
#define KCHUNKS (KDIM / BK)        // 64
#define ROW_BYTES 160              // 128B data + 32B pad (conflict-free LDS.64)
#define STAGE_BYTES (2 * BM * ROW_BYTES)   // A + B = 40960
#define SM_BOFF (BM * ROW_BYTES)           // 20480
#define SMEM_TOTAL (2 * STAGE_BYTES)       // 81920

// ---------------- device scratch (tf32-rna + k-pair-permuted) ----------------
__device__ float g_H  [(size_t)NROWS * G_DIM];
__device__ float g_xc [(size_t)NROWS * D_H];
__device__ float g_w1c[(size_t)G_DIM * D_H];
__device__ float g_w2c[(size_t)FLATC * G_DIM];

__device__ __forceinline__ float silu_f(float v) { return v / (1.0f + __expf(-v)); }
__device__ __forceinline__ uint32_t f2tf32(float x) {
    uint32_t r; asm("cvt.rna.tf32.f32 %0, %1;" : "=r"(r) : "f"(x)); return r;
}
__device__ __forceinline__ float rnd_tf32(float x) { return __uint_as_float(f2tf32(x)); }

__device__ __forceinline__ void cp_async16(uint32_t dst, const void* src) {
    asm volatile("cp.async.cg.shared.global [%0], [%1], 16;" :: "r"(dst), "l"(src));
}
__device__ __forceinline__ uint32_t smem_u32(const void* p) {
    uint32_t a;
    asm("{ .reg .u64 t; cvta.to.shared.u64 t, %1; cvt.u32.u64 %0, t; }" : "=r"(a) : "l"(p));
    return a;
}
__device__ __forceinline__ void lds64(uint32_t addr, uint32_t& x, uint32_t& y) {
    asm volatile("ld.shared.v2.b32 {%0,%1}, [%2];" : "=r"(x), "=r"(y) : "r"(addr));
}
__device__ __forceinline__ void mma_tf32(float c[4], uint32_t a0, uint32_t a1,
                                         uint32_t a2, uint32_t a3,
                                         uint32_t b0, uint32_t b1) {
    asm volatile(
        "mma.sync.aligned.m16n8k8.row.col.f32.tf32.tf32.f32 "
        "{%0,%1,%2,%3}, {%4,%5,%6,%7}, {%8,%9}, {%0,%1,%2,%3};"
        : "+f"(c[0]), "+f"(c[1]), "+f"(c[2]), "+f"(c[3])
        : "r"(a0), "r"(a1), "r"(a2), "r"(a3), "r"(b0), "r"(b1));
}

// ---------------- pre-convert: fp32 -> tf32(rna), k-pair permutation ----------------
// Per 8-block of k: output positions [k0,k4,k1,k5,k2,k6,k3,k7].
// Permuting the reduction index identically in both GEMM operands leaves the
// dot product unchanged, but makes each mma thread's (k, k+4) pair adjacent
// in smem -> LDS.64 fragment loads.
template <int WHICH>
__global__ __launch_bounds__(256)
void cvt_perm_kernel(const float* __restrict__ src, int n8) {
    float* dst = (WHICH == 0) ? g_xc : (WHICH == 1) ? g_w1c : g_w2c;
    int i = blockIdx.x * blockDim.x + threadIdx.x;
    if (i < n8) {
        const float4* s = (const float4*)src + i * 2;
        float4 lo = s[0], hi = s[1];
        float4 o0, o1;
        o0.x = rnd_tf32(lo.x); o0.y = rnd_tf32(hi.x);   // k0,k4
        o0.z = rnd_tf32(lo.y); o0.w = rnd_tf32(hi.y);   // k1,k5
        o1.x = rnd_tf32(lo.z); o1.y = rnd_tf32(hi.z);   // k2,k6
        o1.z = rnd_tf32(lo.w); o1.w = rnd_tf32(hi.w);   // k3,k7
        float4* d = (float4*)dst + i * 2;
        d[0] = o0; d[1] = o1;
    }
}

// ---------------- tile loader: A 128xBK + B 128xBK via cp.async ----------------
__device__ __forceinline__ void load_chunk(const float* __restrict__ A,
                                           const float* __restrict__ B,
                                           uint32_t stagebase, int k0,
                                           int row0, int col0, int tid) {
#pragma unroll
    for (int j = 0; j < 4; j++) {
        int idx = tid + 256 * j;
        int r = idx >> 3, c = idx & 7;
        cp_async16(stagebase + r * ROW_BYTES + c * 16,
                   A + (size_t)(row0 + r) * KDIM + k0 + c * 4);
    }
#pragma unroll
    for (int j = 0; j < 4; j++) {
        int idx = tid + 256 * j;
        int r = idx >> 3, c = idx & 7;
        cp_async16(stagebase + SM_BOFF + r * ROW_BYTES + c * 16,
                   B + (size_t)(col0 + r) * KDIM + k0 + c * 4);
    }
}

// ---------------- main GEMM: C[128x128] = A[128x2048] * B[128x2048]^T ----------------
template <int EPI>
__global__ __launch_bounds__(256, 2)
void gemm_mma(const float* __restrict__ X,     // EPI=1: original x
              const float* __restrict__ b2,    // EPI=1
              float* __restrict__ out) {       // EPI=1
    const float* A = (EPI == 0) ? (const float*)g_xc : (const float*)g_H;
    const float* B = (EPI == 0) ? (const float*)g_w1c : (const float*)g_w2c;

    extern __shared__ char smem[];
    const uint32_t sb = smem_u32(smem);
    const int tid  = threadIdx.x;
    const int lane = tid & 31;
    const int warp = tid >> 5;
    const int wm = warp & 3;
    const int wn = warp >> 2;
    const int row0 = blockIdx.y * BM;
    const int col0 = blockIdx.x * BN;
    const int rq = lane >> 2;       // 0..7
    const int kq = lane & 3;        // 0..3

    float acc[2][8][4];
#pragma unroll
    for (int i = 0; i < 2; i++)
#pragma unroll
        for (int j = 0; j < 8; j++)
#pragma unroll
            for (int k = 0; k < 4; k++) acc[i][j][k] = 0.0f;

    // prologue: chunk 0 -> buf 0
    load_chunk(A, B, sb, 0, row0, col0, tid);
    asm volatile("cp.async.commit_group;" ::: "memory");

    for (int i = 0; i < KCHUNKS; i++) {
        if (i + 1 < KCHUNKS) {
            load_chunk(A, B, sb + ((i + 1) & 1) * STAGE_BYTES, (i + 1) * BK, row0, col0, tid);
            asm volatile("cp.async.commit_group;" ::: "memory");
            asm volatile("cp.async.wait_group 1;" ::: "memory");
        } else {
            asm volatile("cp.async.wait_group 0;" ::: "memory");
        }
        __syncthreads();

        const uint32_t aB = sb + (i & 1) * STAGE_BYTES;
        const uint32_t bB = aB + SM_BOFF;
        const uint32_t arow0 = wm * 32 + rq;
        const uint32_t brow0 = wn * 64 + rq;

#pragma unroll
        for (int s = 0; s < 4; s++) {
            const uint32_t koff = s * 32 + kq * 8;
            uint32_t af[2][4];
#pragma unroll
            for (int mt = 0; mt < 2; mt++) {
                uint32_t r = arow0 + mt * 16;
                lds64(aB + r * ROW_BYTES + koff, af[mt][0], af[mt][2]);          // (a0,a2)
                lds64(aB + (r + 8) * ROW_BYTES + koff, af[mt][1], af[mt][3]);    // (a1,a3)
            }
            uint32_t bf[8][2];
#pragma unroll
            for (int nt = 0; nt < 8; nt++) {
                lds64(bB + (brow0 + nt * 8) * ROW_BYTES + koff, bf[nt][0], bf[nt][1]);
            }
#pragma unroll
            for (int mt = 0; mt < 2; mt++)
#pragma unroll
                for (int nt = 0; nt < 8; nt++)
                    mma_tf32(acc[mt][nt], af[mt][0], af[mt][1], af[mt][2], af[mt][3],
                             bf[nt][0], bf[nt][1]);
        }
        __syncthreads();   // protect buffer (i+1)&1's overwrite next iteration
    }

    // ---------------- epilogue ----------------
    const int q = kq;

    if (EPI == 0) {
        // silu -> g_H, tf32-rounded, k-pair-permuted (g_H is GEMM2's A).
        // perm within each 8-col block: pos(c) = 2*(c&3) + (c>>2)
        const int c0 = 2 * q;
        const int c1 = 2 * q + 1;
        const int p0 = 2 * (c0 & 3) + (c0 >> 2);
        const int p1 = 2 * (c1 & 3) + (c1 >> 2);
#pragma unroll
        for (int mt = 0; mt < 2; mt++) {
            int n = row0 + wm * 32 + mt * 16 + rq;
#pragma unroll
            for (int nt = 0; nt < 8; nt++) {
                int gb = col0 + wn * 64 + nt * 8;
                float* d0 = g_H + (size_t)n * G_DIM + gb;
                float* d1 = g_H + (size_t)(n + 8) * G_DIM + gb;
                d0[p0] = rnd_tf32(silu_f(acc[mt][nt][0]));
                d0[p1] = rnd_tf32(silu_f(acc[mt][nt][1]));
                d1[p0] = rnd_tf32(silu_f(acc[mt][nt][2]));
                d1[p1] = rnd_tf32(silu_f(acc[mt][nt][3]));
            }
        }
    } else {
        // bias + causal depthwise conv + silu -> out (round-3-verified logic)
        const int halfd = q >> 1;
        const int wa = (q & 1) * 2;
#pragma unroll
        for (int nt = 0; nt < 8; nt++) {
            const int cb = col0 + wn * 64 + nt * 8;
            const int d  = (cb >> 2) + halfd;
            const float bias0 = b2[cb + 2 * q];
            const float bias1 = b2[cb + 2 * q + 1];
#pragma unroll
            for (int mt = 0; mt < 2; mt++) {
#pragma unroll
                for (int h = 0; h < 2; h++) {
                    const int n = row0 + wm * 32 + mt * 16 + rq + h * 8;
                    const int bb = n >> 12;
                    const int t  = n & (T_LEN - 1);
                    const float k0 = acc[mt][nt][2 * h + 0] + bias0;
                    const float k1 = acc[mt][nt][2 * h + 1] + bias1;
                    const float* xb = X + (size_t)bb * T_LEN * D_H + d;
                    float partial = 0.0f;
                    const int tt0 = t - (KW - 1) + wa;
                    if (tt0 >= 0)     partial = fmaf(xb[(size_t)tt0 * D_H], k0, partial);
                    if (tt0 + 1 >= 0) partial = fmaf(xb[(size_t)(tt0 + 1) * D_H], k1, partial);
                    const float tot = partial + __shfl_xor_sync(0xffffffffu, partial, 1);
                    if ((q & 1) == 0)
                        out[(size_t)n * D_H + d] = silu_f(tot);
                }
            }
        }
    }
}

// ---------------------------------------------------------------------------
extern "C" void kernel_launch(void* const* d_in, const int* in_sizes, int n_in,
                              void* d_out, int out_size) {
    const float* x  = (const float*)d_in[0];
    const float* w1 = (const float*)d_in[1];
    const float* w2 = (const float*)d_in[2];
    const float* b2 = (const float*)d_in[3];
    float* out = (float*)d_out;

    static bool attr_done = false;
    if (!attr_done) {
        cudaFuncSetAttribute(gemm_mma<0>, cudaFuncAttributeMaxDynamicSharedMemorySize, SMEM_TOTAL);
        cudaFuncSetAttribute(gemm_mma<1>, cudaFuncAttributeMaxDynamicSharedMemorySize, SMEM_TOTAL);
        attr_done = true;
    }

    // pre-convert (tf32-rna) + k-pair permute
    cvt_perm_kernel<0><<<(NROWS * D_H / 8 + 255) / 256, 256>>>(x,  NROWS * D_H / 8);
    cvt_perm_kernel<1><<<(G_DIM * D_H / 8 + 255) / 256, 256>>>(w1, G_DIM * D_H / 8);
    cvt_perm_kernel<2><<<(FLATC * G_DIM / 8 + 255) / 256, 256>>>(w2, FLATC * G_DIM / 8);

    dim3 blk(256);
    dim3 g1(G_DIM / BN, NROWS / BM);    // (16, 64)
    gemm_mma<0><<<g1, blk, SMEM_TOTAL>>>(nullptr, nullptr, nullptr);

    dim3 g2(FLATC / BN, NROWS / BM);    // (64, 64)
    gemm_mma<1><<<g2, blk, SMEM_TOTAL>>>(x, b2, out);
}